// round 3
// baseline (speedup 1.0000x reference)
#include <cuda_runtime.h>

#define NN     512
#define LROWS  4
#define NCTA   (NN / LROWS)   // 128 CTAs, single wave
#define CTH    512            // compute threads: thread t <-> column t
#define NTH    544            // + 1 fetcher warp
#define RING   8              // SMEM row ring depth

// Persistent state (device globals: allocation-free).
__device__ float g_rows[NN * NN];   // row k as published at step k
__device__ int   g_flag[NN];        // per-row published flags (reset each run)
__device__ int   g_done;            // completion counter for end-of-run reset
__device__ float g_part[NCTA * 4];  // per-CTA partials

static __device__ __forceinline__ float fex2(float x) {
    float y; asm("ex2.approx.f32 %0, %1;" : "=f"(y) : "f"(x)); return y;
}
static __device__ __forceinline__ int ld_acq_gpu(const int* p) {
    int v; asm volatile("ld.acquire.gpu.b32 %0, [%1];" : "=r"(v) : "l"(p) : "memory"); return v;
}
static __device__ __forceinline__ void st_rel_gpu(int* p, int v) {
    asm volatile("st.release.gpu.b32 [%0], %1;" :: "l"(p), "r"(v) : "memory");
}
static __device__ __forceinline__ int ld_acq_cta(const int* p) {
    int v; asm volatile("ld.acquire.cta.b32 %0, [%1];" : "=r"(v) : "l"(p) : "memory"); return v;
}
static __device__ __forceinline__ void st_rel_cta(int* p, int v) {
    asm volatile("st.release.cta.b32 [%0], %1;" :: "l"(p), "r"(v) : "memory");
}
// Named barrier: compute warps only (fetcher warp never joins)
#define CBAR() asm volatile("bar.sync 1, 512;" ::: "memory")

// C2*log2(1+e) ~= e*(P0 + e*(P1 + e*P2)), endpoint-exact at e=0,1
#define PC0  0.0989386f
#define PC1 (-0.0417585f)
#define PC2  0.0121347f
#define C1   14.4269504088896f   // 1/(gamma*ln2)

__global__ void __launch_bounds__(NTH, 1) fw_kernel(
    const float* __restrict__ soft, const float* __restrict__ orig,
    const float* __restrict__ dist, const float* __restrict__ flow)
{
    __shared__ float srow[RING][NN];   // fetched rows (16KB)
    __shared__ int   rflag[RING];      // stage s holds row k  <=>  rflag[s]==k+1
    __shared__ int   scons;            // number of steps fully consumed
    __shared__ float a_s[2][LROWS];    // parity-buffered column-k broadcast
    __shared__ float r4[16][4];

    const int tid = threadIdx.x;
    const int cta = blockIdx.x;
    const int r0  = cta * LROWS;

    if (tid == 0) {
        scons = 0;
#pragma unroll
        for (int s = 0; s < RING; s++) rflag[s] = 0;
    }
    __syncthreads();   // ONLY full-CTA barrier (before role split)

    if (tid >= CTH) {
        // ───────────── fetcher warp ─────────────
        const int lane = tid - CTH;
        for (int k = 0; k < NN; k++) {
            if (k >= r0 && k < r0 + LROWS) continue;          // own rows: not needed
            if (k >= RING) {                                   // stage reuse gate
                while (ld_acq_cta(&scons) < k - RING + 1) {}
            }
            if (lane == 0) { while (ld_acq_gpu(&g_flag[k]) == 0) {} }
            __syncwarp();
            const float4* src = reinterpret_cast<const float4*>(g_rows + (size_t)k * NN);
            float4* dst = reinterpret_cast<float4*>(srow[k & (RING - 1)]);
            float4 a0 = __ldcg(src + lane);
            float4 a1 = __ldcg(src + 32 + lane);
            float4 a2 = __ldcg(src + 64 + lane);
            float4 a3 = __ldcg(src + 96 + lane);
            dst[lane] = a0; dst[32 + lane] = a1; dst[64 + lane] = a2; dst[96 + lane] = a3;
            __syncwarp();
            if (lane == 0) st_rel_cta(&rflag[k & (RING - 1)], k + 1);
        }
        return;
    }

    // ───────────── compute threads (t = column) ─────────────
    const int t    = tid;
    const int lane = t & 31;
    const int wid  = t >> 5;

    float wv[LROWS], dv[LROWS];
    float accC = 0.f, accM = 0.f, accE = 0.f;
#pragma unroll
    for (int lr = 0; lr < LROWS; lr++) {
        int r   = r0 + lr;
        float s = soft[r * NN + t];
        float d = dist[r * NN + t];
        float o = orig[r * NN + t];
        dv[lr]  = d;
        wv[lr]  = (r == t) ? 0.f : (d / (s + 1e-4f));
        accC    = fmaf(s, d, accC);
        accM    = fmaf(s, 1.f - o, accM);
        float z = s * (((r == t) ? 1.f : 0.f) - s);
        accE    = fmaf(z, z, accE);
    }

    // CTA 0 pre-publishes row 0 (flag released after iter-0 barrier)
    if (r0 == 0) {
        g_rows[t] = wv[0];
        __threadfence();
    }

    for (int k = 0; k < NN; k++) {
        const int  p   = k & 1;
        const int  st  = k & (RING - 1);
        const int  lrk = k - r0;
        const bool own = (lrk >= 0) && (lrk < LROWS);

        float rk;
        if (own) {
            rk = (lrk == 0) ? wv[0] : (lrk == 1) ? wv[1] : (lrk == 2) ? wv[2] : wv[3];
        } else {
            while (ld_acq_cta(&rflag[st]) != k + 1) {}
            rk = srow[st][t];
        }

        if (t == k) {
#pragma unroll
            for (int lr = 0; lr < LROWS; lr++) a_s[p][lr] = wv[lr];
        }
        CBAR();   // a_s visible; publish stores (from end of iter k-1) + fences done

        if (own && t == 0) st_rel_gpu(&g_flag[k], 1);   // release row k to other CTAs

        // softmin update (4 elements in registers)
#pragma unroll
        for (int lr = 0; lr < LROWS; lr++) {
            float a   = a_s[p][lr];
            float pth = a + rk;
            float w   = wv[lr];
            float m   = fminf(w, pth);
            float dif = w - pth;
            float x   = fminf(dif, -dif) * C1;      // -|w-p| * C1
            float e   = fex2(x);
            float q   = fmaf(PC2, e, PC1);
            q         = fmaf(q, e, PC0);
            wv[lr]    = fmaf(-e, q, m);             // m - C2*log2(1+e)
        }

        if (t == 0) st_rel_cta(&scons, k + 1);      // stage st reusable

        // early publish of row k+1 if we own it (flag released after next bar)
        const int kn  = k + 1;
        const int lrn = kn - r0;
        if (lrn >= 0 && lrn < LROWS) {
            g_rows[kn * NN + t] =
                (lrn == 0) ? wv[0] : (lrn == 1) ? wv[1] : (lrn == 2) ? wv[2] : wv[3];
            __threadfence();
        }
    }

    // Epilogue: utility term from shortest paths
    float accU = 0.f;
#pragma unroll
    for (int lr = 0; lr < LROWS; lr++) {
        int r    = r0 + lr;
        float d  = dv[lr];
        float f  = flow[r * NN + t];
        float sp = wv[lr];
        float choice = 1.0f / (1.0f + expf(fmaf(0.005f, sp, -0.01f * d)));
        float ds  = fmaf(-0.5f, sp, d);
        float ug  = f * choice * ds;
        float elu = (ug > 0.f) ? ug : (expf(ug) - 1.0f);
        accU += elu + 1.0f;
    }

#pragma unroll
    for (int o = 16; o > 0; o >>= 1) {
        accC += __shfl_down_sync(0xffffffffu, accC, o);
        accU += __shfl_down_sync(0xffffffffu, accU, o);
        accE += __shfl_down_sync(0xffffffffu, accE, o);
        accM += __shfl_down_sync(0xffffffffu, accM, o);
    }
    if (lane == 0) { r4[wid][0] = accC; r4[wid][1] = accU; r4[wid][2] = accE; r4[wid][3] = accM; }
    CBAR();
    if (t < 16) {
        float a = r4[t][0], b = r4[t][1], c = r4[t][2], d = r4[t][3];
#pragma unroll
        for (int o = 8; o > 0; o >>= 1) {
            a += __shfl_down_sync(0xffffu, a, o);
            b += __shfl_down_sync(0xffffu, b, o);
            c += __shfl_down_sync(0xffffu, c, o);
            d += __shfl_down_sync(0xffffu, d, o);
        }
        if (t == 0) {
            g_part[cta * 4 + 0] = a; g_part[cta * 4 + 1] = b;
            g_part[cta * 4 + 2] = c; g_part[cta * 4 + 3] = d;
        }
    }

    // End-of-run reset (last CTA) for the next graph replay
    CBAR();
    __threadfence();
    if (t == 0) {
        int prev = atomicAdd(&g_done, 1);
        if (prev == NCTA - 1) {
            for (int i = 0; i < NN; i++) g_flag[i] = 0;
            __threadfence();
            g_done = 0;
        }
    }
}

__global__ void fin_kernel(const int* __restrict__ ep, float* __restrict__ out)
{
    const int t = threadIdx.x;           // 128 threads = NCTA
    const int lane = t & 31, wid = t >> 5;
    __shared__ float s4[4][4];
    float c = g_part[t * 4 + 0], u = g_part[t * 4 + 1];
    float e = g_part[t * 4 + 2], m = g_part[t * 4 + 3];
#pragma unroll
    for (int o = 16; o > 0; o >>= 1) {
        c += __shfl_down_sync(0xffffffffu, c, o);
        u += __shfl_down_sync(0xffffffffu, u, o);
        e += __shfl_down_sync(0xffffffffu, e, o);
        m += __shfl_down_sync(0xffffffffu, m, o);
    }
    if (lane == 0) { s4[wid][0] = c; s4[wid][1] = u; s4[wid][2] = e; s4[wid][3] = m; }
    __syncthreads();
    if (t == 0) {
        float C = s4[0][0] + s4[1][0] + s4[2][0] + s4[3][0];
        float U = s4[0][1] + s4[1][1] + s4[2][1] + s4[3][1];
        float E = s4[0][2] + s4[1][2] + s4[2][2] + s4[3][2];
        float M = s4[0][3] + s4[1][3] + s4[2][3] + s4[3][3];
        int epoch = *ep;
        int idx = (epoch >= 0) + (epoch >= 10) + (epoch >= 50);
        const float lv[4] = {0.0f, 0.05f, 0.1f, 1.0f};
        out[0] = C + U + lv[idx] * E + 10000.0f * M;
    }
}

extern "C" void kernel_launch(void* const* d_in, const int* in_sizes, int n_in,
                              void* d_out, int out_size)
{
    (void)in_sizes; (void)n_in; (void)out_size;
    const float* soft = (const float*)d_in[0];
    const float* orig = (const float*)d_in[1];
    const float* dist = (const float*)d_in[2];
    const float* flow = (const float*)d_in[3];
    const int*   ep   = (const int*)d_in[4];

    fw_kernel<<<NCTA, NTH>>>(soft, orig, dist, flow);
    fin_kernel<<<1, NCTA>>>(ep, (float*)d_out);
}